// round 2
// baseline (speedup 1.0000x reference)
#include <cuda_runtime.h>
#include <math.h>

// ---------------- problem constants ----------------
#define S_LEN   2048
#define D_MODEL 4096
#define H_HEADS 32
#define QLORA   1536
#define KVLORA  512
#define NOPE_D  128
#define ROPE_D  64
#define QKH     192          // NOPE + ROPE
#define VH      128
#define QKF     576          // KVLORA + ROPE (merged latent+rope feature dim)
#define QDIM    (H_HEADS*QKH)   // 6144

// ---------------- scratch (device globals; no allocation) ----------------
__device__ float g_qa[S_LEN * QLORA];
__device__ float g_q [S_LEN * QDIM];
__device__ float g_kv[S_LEN * QKF];
__device__ float g_kf[S_LEN * QKF];                                    // kv_c | k_rot
__device__ float g_qf[(long long)H_HEADS * S_LEN * QKF];               // q_latent | q_rope
__device__ float g_scores[(long long)H_HEADS * S_LEN * S_LEN];
__device__ float g_ctxl[(long long)H_HEADS * S_LEN * KVLORA];
__device__ float g_ctx[S_LEN * D_MODEL];

// ---------------- block reductions ----------------
__device__ __forceinline__ float blk_sum(float v) {
    __shared__ float sm[32];
    int lane = threadIdx.x & 31, w = threadIdx.x >> 5;
    #pragma unroll
    for (int o = 16; o; o >>= 1) v += __shfl_down_sync(0xffffffffu, v, o);
    if (lane == 0) sm[w] = v;
    __syncthreads();
    int nw = (blockDim.x + 31) >> 5;
    v = (threadIdx.x < nw) ? sm[threadIdx.x] : 0.f;
    if (w == 0) {
        #pragma unroll
        for (int o = 16; o; o >>= 1) v += __shfl_down_sync(0xffffffffu, v, o);
        if (lane == 0) sm[0] = v;
    }
    __syncthreads();
    float r = sm[0];
    __syncthreads();
    return r;
}

__device__ __forceinline__ float blk_max(float v) {
    __shared__ float sm[32];
    int lane = threadIdx.x & 31, w = threadIdx.x >> 5;
    #pragma unroll
    for (int o = 16; o; o >>= 1) v = fmaxf(v, __shfl_down_sync(0xffffffffu, v, o));
    if (lane == 0) sm[w] = v;
    __syncthreads();
    int nw = (blockDim.x + 31) >> 5;
    v = (threadIdx.x < nw) ? sm[threadIdx.x] : -3.4e38f;
    if (w == 0) {
        #pragma unroll
        for (int o = 16; o; o >>= 1) v = fmaxf(v, __shfl_down_sync(0xffffffffu, v, o));
        if (lane == 0) sm[0] = v;
    }
    __syncthreads();
    float r = sm[0];
    __syncthreads();
    return r;
}

// ---------------- batched 128x128x8 SGEMM, 8x8 micro-tiles ----------------
// C[bz] = alpha * A[bz] (2048 x K) * op(B[bz]) (K x N)
//   TB=true : B is (N,K) row-major -> A @ B^T
//   TB=false: B is (K,N) row-major
// Assumptions (hold for every call site): M == 2048 (multiple of 128),
// K multiple of 8, N multiple of 4, all row strides multiples of 4 floats.
// causal_skip : skip output tiles entirely above the diagonal
// causal_klim : truncate the K loop at bm+128 (A columns beyond are exact zeros)
template<bool TB>
__global__ void __launch_bounds__(256, 2)
sgemm128(const float* __restrict__ A, const float* __restrict__ B, float* __restrict__ C,
         int N, int K, int lda, int ldb, int ldc,
         long long sA, long long sB, long long sC,
         float alpha, int causal_skip, int causal_klim)
{
    const int bm = blockIdx.y * 128, bn = blockIdx.x * 128;
    if (causal_skip && bn > bm + 127) return;
    const long long bz = blockIdx.z;
    A += bz * sA; B += bz * sB; C += bz * sC;

    __shared__ __align__(16) float As[8][128];
    __shared__ __align__(16) float Bs[8][128];

    const int tid = threadIdx.x;
    const int tx = tid & 15, ty = tid >> 4;          // 16x16 thread grid
    float acc[8][8] = {};

    const int Keff = causal_klim ? ((K < bm + 128) ? K : bm + 128) : K;

    // A-load indices: each thread loads one float4 along K
    const int a_r = tid >> 1;            // 0..127
    const int a_c = (tid & 1) * 4;       // 0 or 4
    // B-load indices
    const int bt_r = tid >> 1;           // TB: row in B (N dim)
    const int bt_c = (tid & 1) * 4;      // TB: col in B (K dim)
    const int bn_k = tid >> 5;           // !TB: k row 0..7
    const int bn_n = (tid & 31) * 4;     // !TB: n col 0..124

    for (int k0 = 0; k0 < Keff; k0 += 8) {
        // load A tile (128 x 8), transpose into As[k][m]
        {
            float4 v = *(const float4*)&A[(long long)(bm + a_r) * lda + (k0 + a_c)];
            As[a_c + 0][a_r] = v.x;
            As[a_c + 1][a_r] = v.y;
            As[a_c + 2][a_r] = v.z;
            As[a_c + 3][a_r] = v.w;
        }
        // load B tile into Bs[k][n]
        if (TB) {
            int gn = bn + bt_r;
            float4 v = make_float4(0.f, 0.f, 0.f, 0.f);
            if (gn < N) v = *(const float4*)&B[(long long)gn * ldb + (k0 + bt_c)];
            Bs[bt_c + 0][bt_r] = v.x;
            Bs[bt_c + 1][bt_r] = v.y;
            Bs[bt_c + 2][bt_r] = v.z;
            Bs[bt_c + 3][bt_r] = v.w;
        } else {
            int gn = bn + bn_n;
            float4 v = make_float4(0.f, 0.f, 0.f, 0.f);
            if (gn < N) v = *(const float4*)&B[(long long)(k0 + bn_k) * ldb + gn];
            *(float4*)&Bs[bn_k][bn_n] = v;
        }
        __syncthreads();

        #pragma unroll
        for (int k = 0; k < 8; k++) {
            float4 a0 = *(const float4*)&As[k][ty * 8];
            float4 a1 = *(const float4*)&As[k][ty * 8 + 4];
            float4 b0 = *(const float4*)&Bs[k][tx * 8];
            float4 b1 = *(const float4*)&Bs[k][tx * 8 + 4];
            float a[8] = {a0.x, a0.y, a0.z, a0.w, a1.x, a1.y, a1.z, a1.w};
            float b[8] = {b0.x, b0.y, b0.z, b0.w, b1.x, b1.y, b1.z, b1.w};
            #pragma unroll
            for (int i = 0; i < 8; i++)
                #pragma unroll
                for (int j = 0; j < 8; j++)
                    acc[i][j] = fmaf(a[i], b[j], acc[i][j]);
        }
        __syncthreads();
    }

    // epilogue: vectorized stores with N guard (N multiple of 4)
    #pragma unroll
    for (int i = 0; i < 8; i++) {
        long long gm = bm + ty * 8 + i;
        float* crow = C + gm * ldc;
        #pragma unroll
        for (int jv = 0; jv < 2; jv++) {
            int gn = bn + tx * 8 + jv * 4;
            if (gn < N) {
                float4 v = make_float4(alpha * acc[i][jv * 4 + 0],
                                       alpha * acc[i][jv * 4 + 1],
                                       alpha * acc[i][jv * 4 + 2],
                                       alpha * acc[i][jv * 4 + 3]);
                *(float4*)&crow[gn] = v;
            }
        }
    }
}

// ---------------- rmsnorm over rows (in place) ----------------
__global__ void rmsnorm_kernel(float* __restrict__ x, const float* __restrict__ g, int n) {
    float* p = x + (long long)blockIdx.x * n;
    float ss = 0.f;
    for (int i = threadIdx.x; i < n; i += blockDim.x) { float v = p[i]; ss += v * v; }
    ss = blk_sum(ss);
    float scale = rsqrtf(ss / (float)n + 1e-6f);
    for (int i = threadIdx.x; i < n; i += blockDim.x) p[i] = p[i] * scale * g[i];
}

// ---------------- kv post-process: rmsnorm(kv_c) | rope(k_rot) -> g_kf ----------------
__global__ void kv_proc_kernel(const float* __restrict__ kv, const float* __restrict__ g,
                               const float* __restrict__ cosb, const float* __restrict__ sinb,
                               float* __restrict__ kf) {
    int s = blockIdx.x;
    const float* r = kv + (long long)s * QKF;
    float* o = kf + (long long)s * QKF;
    float ss = 0.f;
    for (int i = threadIdx.x; i < KVLORA; i += blockDim.x) { float v = r[i]; ss += v * v; }
    ss = blk_sum(ss);
    float scale = rsqrtf(ss / (float)KVLORA + 1e-6f);
    for (int i = threadIdx.x; i < KVLORA; i += blockDim.x) o[i] = r[i] * scale * g[i];
    for (int i = threadIdx.x; i < ROPE_D; i += blockDim.x) {
        float x = r[KVLORA + i];
        float rot = (i < ROPE_D / 2) ? -r[KVLORA + i + ROPE_D / 2] : r[KVLORA + i - ROPE_D / 2];
        o[KVLORA + i] = x * cosb[s * ROPE_D + i] + rot * sinb[s * ROPE_D + i];
    }
}

// ---------------- q rope: write rope part of q into g_qf[h][s][512..575] ----------------
__global__ void q_rope_kernel(const float* __restrict__ q, const float* __restrict__ cosb,
                              const float* __restrict__ sinb, float* __restrict__ qf) {
    int s = blockIdx.x, h = blockIdx.y, i = threadIdx.x;  // 64 threads
    const float* base = q + (long long)s * QDIM + h * QKH + NOPE_D;
    float x = base[i];
    float rot = (i < ROPE_D / 2) ? -base[i + ROPE_D / 2] : base[i - ROPE_D / 2];
    qf[((long long)h * S_LEN + s) * QKF + KVLORA + i] =
        x * cosb[s * ROPE_D + i] + rot * sinb[s * ROPE_D + i];
}

// ---------------- causal softmax, in place, zeros masked tail ----------------
__global__ void softmax_kernel(float* __restrict__ scores) {
    int q = blockIdx.x, h = blockIdx.y;
    float* row = scores + ((long long)h * S_LEN + q) * S_LEN;
    int len = q + 1;
    float m = -3.4e38f;
    for (int i = threadIdx.x; i < len; i += blockDim.x) m = fmaxf(m, row[i]);
    m = blk_max(m);
    float sum = 0.f;
    for (int i = threadIdx.x; i < len; i += blockDim.x) {
        float e = __expf(row[i] - m);
        row[i] = e;
        sum += e;
    }
    sum = blk_sum(sum);
    float inv = 1.0f / sum;
    for (int i = threadIdx.x; i < S_LEN; i += blockDim.x)
        row[i] = (i < len) ? row[i] * inv : 0.f;
}

// ---------------- launch ----------------
extern "C" void kernel_launch(void* const* d_in, const int* in_sizes, int n_in,
                              void* d_out, int out_size) {
    const float* hs     = (const float*)d_in[0];
    const float* cosb   = (const float*)d_in[1];
    const float* sinb   = (const float*)d_in[2];
    const float* w_q_a  = (const float*)d_in[3];
    const float* gq_a   = (const float*)d_in[4];
    const float* w_q_b  = (const float*)d_in[5];
    const float* w_kv_a = (const float*)d_in[6];
    const float* gkv_a  = (const float*)d_in[7];
    const float* w_uk_t = (const float*)d_in[8];
    const float* w_uv   = (const float*)d_in[9];
    const float* w_o    = (const float*)d_in[10];
    float* out = (float*)d_out;

    float *qa, *q, *kv, *kf, *qf, *scores, *ctxl, *ctx;
    cudaGetSymbolAddress((void**)&qa,     g_qa);
    cudaGetSymbolAddress((void**)&q,      g_q);
    cudaGetSymbolAddress((void**)&kv,     g_kv);
    cudaGetSymbolAddress((void**)&kf,     g_kf);
    cudaGetSymbolAddress((void**)&qf,     g_qf);
    cudaGetSymbolAddress((void**)&scores, g_scores);
    cudaGetSymbolAddress((void**)&ctxl,   g_ctxl);
    cudaGetSymbolAddress((void**)&ctx,    g_ctx);

    dim3 blk(256);
    const int MT = S_LEN / 128;  // 16 row tiles
    const float scale = 1.0f / sqrtf((float)QKH);
    #define NT(n) (((n) + 127) / 128)

    // 1) q_a = hs @ w_q_a^T   [2048,1536]
    sgemm128<true><<<dim3(NT(QLORA), MT, 1), blk>>>(
        hs, w_q_a, qa, QLORA, D_MODEL, D_MODEL, D_MODEL, QLORA,
        0, 0, 0, 1.f, 0, 0);

    // 2) rmsnorm(q_a)
    rmsnorm_kernel<<<S_LEN, 256>>>(qa, gq_a, QLORA);

    // 3) q = q_a @ w_q_b^T    [2048,6144]
    sgemm128<true><<<dim3(NT(QDIM), MT, 1), blk>>>(
        qa, w_q_b, q, QDIM, QLORA, QLORA, QLORA, QDIM,
        0, 0, 0, 1.f, 0, 0);

    // 4) kv = hs @ w_kv_a^T   [2048,576]
    sgemm128<true><<<dim3(NT(QKF), MT, 1), blk>>>(
        hs, w_kv_a, kv, QKF, D_MODEL, D_MODEL, D_MODEL, QKF,
        0, 0, 0, 1.f, 0, 0);

    // 5) kf = [rmsnorm(kv_c) | rope(k_rot)]
    kv_proc_kernel<<<S_LEN, 256>>>(kv, gkv_a, cosb, sinb, kf);

    // 6) q_latent[h] = q_nope[:,h,:] @ w_uk_t[h]  -> qf[h][:, 0:512]
    sgemm128<false><<<dim3(NT(KVLORA), MT, H_HEADS), blk>>>(
        q, w_uk_t, qf, KVLORA, NOPE_D, QDIM, KVLORA, QKF,
        (long long)QKH, (long long)NOPE_D * KVLORA, (long long)S_LEN * QKF,
        1.f, 0, 0);

    // 7) rope(q_rope) -> qf[h][:, 512:576]
    q_rope_kernel<<<dim3(S_LEN, H_HEADS), 64>>>(q, cosb, sinb, qf);

    // 8) scores[h] = scale * qf[h] @ kf^T, causal tile skip
    sgemm128<true><<<dim3(NT(S_LEN), MT, H_HEADS), blk>>>(
        qf, kf, scores, S_LEN, QKF, QKF, QKF, S_LEN,
        (long long)S_LEN * QKF, 0, (long long)S_LEN * S_LEN,
        scale, /*causal_skip=*/1, 0);

    // 9) causal softmax (zeros masked tail)
    softmax_kernel<<<dim3(S_LEN, H_HEADS), 256>>>(scores);

    // 10) ctxl[h] = probs[h] @ kv_c, K truncated at diagonal
    sgemm128<false><<<dim3(NT(KVLORA), MT, H_HEADS), blk>>>(
        scores, kf, ctxl, KVLORA, S_LEN, S_LEN, QKF, KVLORA,
        (long long)S_LEN * S_LEN, 0, (long long)S_LEN * KVLORA,
        1.f, 0, /*causal_klim=*/1);

    // 11) ctx[:, h*128:(h+1)*128] = ctxl[h] @ w_uv[h]
    sgemm128<false><<<dim3(NT(VH), MT, H_HEADS), blk>>>(
        ctxl, w_uv, ctx, VH, KVLORA, KVLORA, VH, D_MODEL,
        (long long)S_LEN * KVLORA, (long long)KVLORA * VH, (long long)VH,
        1.f, 0, 0);

    // 12) out = ctx @ w_o^T   [2048,4096]
    sgemm128<true><<<dim3(NT(D_MODEL), MT, 1), blk>>>(
        ctx, w_o, out, D_MODEL, D_MODEL, D_MODEL, D_MODEL, D_MODEL,
        0, 0, 0, 1.f, 0, 0);
    #undef NT
}

// round 4
// speedup vs baseline: 1.5121x; 1.5121x over previous
#include <cuda_runtime.h>
#include <cuda_bf16.h>
#include <math.h>

typedef unsigned int uint32;

// ---------------- problem constants ----------------
#define S_LEN   2048
#define D_MODEL 4096
#define H_HEADS 32
#define QLORA   1536
#define KVLORA  512
#define NOPE_D  128
#define ROPE_D  64
#define QKH     192
#define VH      128
#define QKF     576          // KVLORA + ROPE
#define QDIM    (H_HEADS*QKH)   // 6144

// ---------------- scratch ----------------
__device__ float g_qa[S_LEN * QLORA];
__device__ float g_q [S_LEN * QDIM];
__device__ float g_kv[S_LEN * QKF];
__device__ float g_kf[S_LEN * QKF];
__device__ float g_qf[(long long)H_HEADS * S_LEN * QKF];
__device__ float g_scores[(long long)H_HEADS * S_LEN * S_LEN];
__device__ float g_ctxl[(long long)H_HEADS * S_LEN * KVLORA];
__device__ float g_ctx[S_LEN * D_MODEL];

// ---------------- block reductions ----------------
__device__ __forceinline__ float blk_sum(float v) {
    __shared__ float sm[32];
    int lane = threadIdx.x & 31, w = threadIdx.x >> 5;
    #pragma unroll
    for (int o = 16; o; o >>= 1) v += __shfl_down_sync(0xffffffffu, v, o);
    if (lane == 0) sm[w] = v;
    __syncthreads();
    int nw = (blockDim.x + 31) >> 5;
    v = (threadIdx.x < nw) ? sm[threadIdx.x] : 0.f;
    if (w == 0) {
        #pragma unroll
        for (int o = 16; o; o >>= 1) v += __shfl_down_sync(0xffffffffu, v, o);
        if (lane == 0) sm[0] = v;
    }
    __syncthreads();
    float r = sm[0];
    __syncthreads();
    return r;
}

__device__ __forceinline__ float blk_max(float v) {
    __shared__ float sm[32];
    int lane = threadIdx.x & 31, w = threadIdx.x >> 5;
    #pragma unroll
    for (int o = 16; o; o >>= 1) v = fmaxf(v, __shfl_down_sync(0xffffffffu, v, o));
    if (lane == 0) sm[w] = v;
    __syncthreads();
    int nw = (blockDim.x + 31) >> 5;
    v = (threadIdx.x < nw) ? sm[threadIdx.x] : -3.4e38f;
    if (w == 0) {
        #pragma unroll
        for (int o = 16; o; o >>= 1) v = fmaxf(v, __shfl_down_sync(0xffffffffu, v, o));
        if (lane == 0) sm[0] = v;
    }
    __syncthreads();
    float r = sm[0];
    __syncthreads();
    return r;
}

// ---------------- bf16-split tensor-core GEMM ----------------
// C[bz] = alpha * A[bz] (2048 x K) * op(B[bz]) (K x N)
//   TB=true : B is (N,K) row-major -> A @ B^T
//   TB=false: B is (K,N) row-major
// fp32 operands split into bf16 hi+lo; C = Ah*Bh + Al*Bh + Ah*Bl (3 MMAs).
// Assumptions: M == 2048, K % 32 == 0, N % 4 == 0, row strides % 4 == 0.
#define BM  128
#define BN  128
#define BKK 32
#define SMS 40   // padded smem row stride in bf16 elems (conflict-free frag loads)

__device__ __forceinline__ void mma_bf16(float (&c)[4], const uint32 (&a)[4],
                                         uint32 b0, uint32 b1) {
    asm volatile(
        "mma.sync.aligned.m16n8k16.row.col.f32.bf16.bf16.f32 "
        "{%0,%1,%2,%3},{%4,%5,%6,%7},{%8,%9},{%0,%1,%2,%3};\n"
        : "+f"(c[0]), "+f"(c[1]), "+f"(c[2]), "+f"(c[3])
        : "r"(a[0]), "r"(a[1]), "r"(a[2]), "r"(a[3]), "r"(b0), "r"(b1));
}

__device__ __forceinline__ void split_store(__nv_bfloat16* hp, __nv_bfloat16* lp, float x) {
    __nv_bfloat16 h = __float2bfloat16_rn(x);
    *hp = h;
    *lp = __float2bfloat16_rn(x - __bfloat162float(h));
}

template<bool TB>
__global__ void __launch_bounds__(256, 2)
bgemm128(const float* __restrict__ A, const float* __restrict__ B, float* __restrict__ C,
         int N, int K, int lda, int ldb, int ldc,
         long long sA, long long sB, long long sC,
         float alpha, int causal_skip, int causal_klim)
{
    const int bm = blockIdx.y * BM, bn = blockIdx.x * BN;
    if (causal_skip && bn > bm + (BM - 1)) return;
    const long long bz = blockIdx.z;
    A += bz * sA; B += bz * sB; C += bz * sC;

    __shared__ __nv_bfloat16 Ah[BM][SMS];
    __shared__ __nv_bfloat16 Al[BM][SMS];
    __shared__ __nv_bfloat16 Bh[BN][SMS];
    __shared__ __nv_bfloat16 Bl[BN][SMS];

    const int tid  = threadIdx.x;
    const int w    = tid >> 5, lane = tid & 31;
    const int wr   = w >> 2, wc = w & 3;        // warp 2x4 grid: 64x32 warp tile
    const int g    = lane >> 2, tig = lane & 3;

    float acc[4][4][4] = {};                    // [mt][nt][reg]

    const int Keff = causal_klim ? ((K < bm + BM) ? K : bm + BM) : K;

    // loader indices
    const int lr = tid >> 3;          // 0..31 (row group)
    const int lc = (tid & 7) * 4;     // 0..28 (k offset)
    const int n4 = (tid & 31) * 4;    // !TB: n offset 0..124
    const int kk = tid >> 5;          // !TB: k 0..7

    for (int k0 = 0; k0 < Keff; k0 += BKK) {
        // ---- load A tile (128 x 32 fp32) -> split into Ah/Al ----
        #pragma unroll
        for (int i = 0; i < 4; i++) {
            int row = lr + i * 32;
            float4 v = *(const float4*)&A[(long long)(bm + row) * lda + k0 + lc];
            split_store(&Ah[row][lc + 0], &Al[row][lc + 0], v.x);
            split_store(&Ah[row][lc + 1], &Al[row][lc + 1], v.y);
            split_store(&Ah[row][lc + 2], &Al[row][lc + 2], v.z);
            split_store(&Ah[row][lc + 3], &Al[row][lc + 3], v.w);
        }
        // ---- load B tile -> split into Bh/Bl, layout [n][k] ----
        if (TB) {
            #pragma unroll
            for (int i = 0; i < 4; i++) {
                int row = lr + i * 32;
                int gn = bn + row;
                float4 v = make_float4(0.f, 0.f, 0.f, 0.f);
                if (gn < N) v = *(const float4*)&B[(long long)gn * ldb + k0 + lc];
                split_store(&Bh[row][lc + 0], &Bl[row][lc + 0], v.x);
                split_store(&Bh[row][lc + 1], &Bl[row][lc + 1], v.y);
                split_store(&Bh[row][lc + 2], &Bl[row][lc + 2], v.z);
                split_store(&Bh[row][lc + 3], &Bl[row][lc + 3], v.w);
            }
        } else {
            #pragma unroll
            for (int i = 0; i < 4; i++) {
                int k = kk + i * 8;
                float4 v = make_float4(0.f, 0.f, 0.f, 0.f);
                if (bn + n4 < N) v = *(const float4*)&B[(long long)(k0 + k) * ldb + bn + n4];
                split_store(&Bh[n4 + 0][k], &Bl[n4 + 0][k], v.x);
                split_store(&Bh[n4 + 1][k], &Bl[n4 + 1][k], v.y);
                split_store(&Bh[n4 + 2][k], &Bl[n4 + 2][k], v.z);
                split_store(&Bh[n4 + 3][k], &Bl[n4 + 3][k], v.w);
            }
        }
        __syncthreads();

        // ---- compute: 2 k16 steps x 16 mma tiles x 3 split terms ----
        #pragma unroll
        for (int ks = 0; ks < 2; ks++) {
            const int kb = ks * 16 + tig * 2;
            uint32 ah[4][4], al[4][4];
            #pragma unroll
            for (int mt = 0; mt < 4; mt++) {
                int r0 = wr * 64 + mt * 16 + g;
                ah[mt][0] = *(const uint32*)&Ah[r0    ][kb    ];
                ah[mt][1] = *(const uint32*)&Ah[r0 + 8][kb    ];
                ah[mt][2] = *(const uint32*)&Ah[r0    ][kb + 8];
                ah[mt][3] = *(const uint32*)&Ah[r0 + 8][kb + 8];
                al[mt][0] = *(const uint32*)&Al[r0    ][kb    ];
                al[mt][1] = *(const uint32*)&Al[r0 + 8][kb    ];
                al[mt][2] = *(const uint32*)&Al[r0    ][kb + 8];
                al[mt][3] = *(const uint32*)&Al[r0 + 8][kb + 8];
            }
            #pragma unroll
            for (int nt = 0; nt < 4; nt++) {
                int c0 = wc * 32 + nt * 8 + g;
                uint32 bh0 = *(const uint32*)&Bh[c0][kb    ];
                uint32 bh1 = *(const uint32*)&Bh[c0][kb + 8];
                uint32 bl0 = *(const uint32*)&Bl[c0][kb    ];
                uint32 bl1 = *(const uint32*)&Bl[c0][kb + 8];
                #pragma unroll
                for (int mt = 0; mt < 4; mt++) {
                    mma_bf16(acc[mt][nt], ah[mt], bh0, bh1);  // hi*hi
                    mma_bf16(acc[mt][nt], al[mt], bh0, bh1);  // lo*hi
                    mma_bf16(acc[mt][nt], ah[mt], bl0, bl1);  // hi*lo
                }
            }
        }
        __syncthreads();
    }

    // ---- epilogue ----
    #pragma unroll
    for (int mt = 0; mt < 4; mt++) {
        #pragma unroll
        for (int i = 0; i < 2; i++) {
            long long gm = bm + wr * 64 + mt * 16 + g + i * 8;
            float* crow = C + gm * ldc;
            #pragma unroll
            for (int nt = 0; nt < 4; nt++) {
                int gn = bn + wc * 32 + nt * 8 + tig * 2;
                if (gn < N) {
                    float2 v;
                    v.x = alpha * acc[mt][nt][i * 2 + 0];
                    v.y = alpha * acc[mt][nt][i * 2 + 1];
                    *(float2*)&crow[gn] = v;
                }
            }
        }
    }
}

// ---------------- rmsnorm over rows (in place) ----------------
__global__ void rmsnorm_kernel(float* __restrict__ x, const float* __restrict__ g, int n) {
    float* p = x + (long long)blockIdx.x * n;
    float ss = 0.f;
    for (int i = threadIdx.x; i < n; i += blockDim.x) { float v = p[i]; ss += v * v; }
    ss = blk_sum(ss);
    float scale = rsqrtf(ss / (float)n + 1e-6f);
    for (int i = threadIdx.x; i < n; i += blockDim.x) p[i] = p[i] * scale * g[i];
}

// ---------------- kv post-process: rmsnorm(kv_c) | rope(k_rot) ----------------
__global__ void kv_proc_kernel(const float* __restrict__ kv, const float* __restrict__ g,
                               const float* __restrict__ cosb, const float* __restrict__ sinb,
                               float* __restrict__ kf) {
    int s = blockIdx.x;
    const float* r = kv + (long long)s * QKF;
    float* o = kf + (long long)s * QKF;
    float ss = 0.f;
    for (int i = threadIdx.x; i < KVLORA; i += blockDim.x) { float v = r[i]; ss += v * v; }
    ss = blk_sum(ss);
    float scale = rsqrtf(ss / (float)KVLORA + 1e-6f);
    for (int i = threadIdx.x; i < KVLORA; i += blockDim.x) o[i] = r[i] * scale * g[i];
    for (int i = threadIdx.x; i < ROPE_D; i += blockDim.x) {
        float x = r[KVLORA + i];
        float rot = (i < ROPE_D / 2) ? -r[KVLORA + i + ROPE_D / 2] : r[KVLORA + i - ROPE_D / 2];
        o[KVLORA + i] = x * cosb[s * ROPE_D + i] + rot * sinb[s * ROPE_D + i];
    }
}

// ---------------- q rope ----------------
__global__ void q_rope_kernel(const float* __restrict__ q, const float* __restrict__ cosb,
                              const float* __restrict__ sinb, float* __restrict__ qf) {
    int s = blockIdx.x, h = blockIdx.y, i = threadIdx.x;  // 64 threads
    const float* base = q + (long long)s * QDIM + h * QKH + NOPE_D;
    float x = base[i];
    float rot = (i < ROPE_D / 2) ? -base[i + ROPE_D / 2] : base[i - ROPE_D / 2];
    qf[((long long)h * S_LEN + s) * QKF + KVLORA + i] =
        x * cosb[s * ROPE_D + i] + rot * sinb[s * ROPE_D + i];
}

// ---------------- causal softmax, in place, zeros masked tail ----------------
__global__ void softmax_kernel(float* __restrict__ scores) {
    int q = blockIdx.x, h = blockIdx.y;
    float* row = scores + ((long long)h * S_LEN + q) * S_LEN;
    int len = q + 1;
    float m = -3.4e38f;
    for (int i = threadIdx.x; i < len; i += blockDim.x) m = fmaxf(m, row[i]);
    m = blk_max(m);
    float sum = 0.f;
    for (int i = threadIdx.x; i < len; i += blockDim.x) {
        float e = __expf(row[i] - m);
        row[i] = e;
        sum += e;
    }
    sum = blk_sum(sum);
    float inv = 1.0f / sum;
    for (int i = threadIdx.x; i < S_LEN; i += blockDim.x)
        row[i] = (i < len) ? row[i] * inv : 0.f;
}

// ---------------- launch ----------------
extern "C" void kernel_launch(void* const* d_in, const int* in_sizes, int n_in,
                              void* d_out, int out_size) {
    const float* hs     = (const float*)d_in[0];
    const float* cosb   = (const float*)d_in[1];
    const float* sinb   = (const float*)d_in[2];
    const float* w_q_a  = (const float*)d_in[3];
    const float* gq_a   = (const float*)d_in[4];
    const float* w_q_b  = (const float*)d_in[5];
    const float* w_kv_a = (const float*)d_in[6];
    const float* gkv_a  = (const float*)d_in[7];
    const float* w_uk_t = (const float*)d_in[8];
    const float* w_uv   = (const float*)d_in[9];
    const float* w_o    = (const float*)d_in[10];
    float* out = (float*)d_out;

    float *qa, *q, *kv, *kf, *qf, *scores, *ctxl, *ctx;
    cudaGetSymbolAddress((void**)&qa,     g_qa);
    cudaGetSymbolAddress((void**)&q,      g_q);
    cudaGetSymbolAddress((void**)&kv,     g_kv);
    cudaGetSymbolAddress((void**)&kf,     g_kf);
    cudaGetSymbolAddress((void**)&qf,     g_qf);
    cudaGetSymbolAddress((void**)&scores, g_scores);
    cudaGetSymbolAddress((void**)&ctxl,   g_ctxl);
    cudaGetSymbolAddress((void**)&ctx,    g_ctx);

    dim3 blk(256);
    const int MT = S_LEN / 128;
    const float scale = 1.0f / sqrtf((float)QKH);
    #define NT(n) (((n) + 127) / 128)

    // 1) q_a = hs @ w_q_a^T
    bgemm128<true><<<dim3(NT(QLORA), MT, 1), blk>>>(
        hs, w_q_a, qa, QLORA, D_MODEL, D_MODEL, D_MODEL, QLORA,
        0, 0, 0, 1.f, 0, 0);

    // 2) rmsnorm(q_a)
    rmsnorm_kernel<<<S_LEN, 256>>>(qa, gq_a, QLORA);

    // 3) q = q_a @ w_q_b^T
    bgemm128<true><<<dim3(NT(QDIM), MT, 1), blk>>>(
        qa, w_q_b, q, QDIM, QLORA, QLORA, QLORA, QDIM,
        0, 0, 0, 1.f, 0, 0);

    // 4) kv = hs @ w_kv_a^T
    bgemm128<true><<<dim3(NT(QKF), MT, 1), blk>>>(
        hs, w_kv_a, kv, QKF, D_MODEL, D_MODEL, D_MODEL, QKF,
        0, 0, 0, 1.f, 0, 0);

    // 5) kf = [rmsnorm(kv_c) | rope(k_rot)]
    kv_proc_kernel<<<S_LEN, 256>>>(kv, gkv_a, cosb, sinb, kf);

    // 6) q_latent[h] = q_nope[:,h,:] @ w_uk_t[h]
    bgemm128<false><<<dim3(NT(KVLORA), MT, H_HEADS), blk>>>(
        q, w_uk_t, qf, KVLORA, NOPE_D, QDIM, KVLORA, QKF,
        (long long)QKH, (long long)NOPE_D * KVLORA, (long long)S_LEN * QKF,
        1.f, 0, 0);

    // 7) rope(q_rope)
    q_rope_kernel<<<dim3(S_LEN, H_HEADS), 64>>>(q, cosb, sinb, qf);

    // 8) scores[h] = scale * qf[h] @ kf^T, causal tile skip
    bgemm128<true><<<dim3(NT(S_LEN), MT, H_HEADS), blk>>>(
        qf, kf, scores, S_LEN, QKF, QKF, QKF, S_LEN,
        (long long)S_LEN * QKF, 0, (long long)S_LEN * S_LEN,
        scale, /*causal_skip=*/1, 0);

    // 9) causal softmax
    softmax_kernel<<<dim3(S_LEN, H_HEADS), 256>>>(scores);

    // 10) ctxl[h] = probs[h] @ kv_c, K truncated at diagonal
    bgemm128<false><<<dim3(NT(KVLORA), MT, H_HEADS), blk>>>(
        scores, kf, ctxl, KVLORA, S_LEN, S_LEN, QKF, KVLORA,
        (long long)S_LEN * S_LEN, 0, (long long)S_LEN * KVLORA,
        1.f, 0, /*causal_klim=*/1);

    // 11) ctx[:, h*128:(h+1)*128] = ctxl[h] @ w_uv[h]
    bgemm128<false><<<dim3(NT(VH), MT, H_HEADS), blk>>>(
        ctxl, w_uv, ctx, VH, KVLORA, KVLORA, VH, D_MODEL,
        (long long)S_LEN * KVLORA, (long long)KVLORA * VH, (long long)VH,
        1.f, 0, 0);

    // 12) out = ctx @ w_o^T
    bgemm128<true><<<dim3(NT(D_MODEL), MT, 1), blk>>>(
        ctx, w_o, out, D_MODEL, D_MODEL, D_MODEL, D_MODEL, D_MODEL,
        0, 0, 0, 1.f, 0, 0);
    #undef NT
}